// round 2
// baseline (speedup 1.0000x reference)
#include <cuda_runtime.h>

// MultiScaleDeformableAttention (bs=8, nq=900, nh=8, d=32, nl=4, npt=4)
// value:              (8, 22223, 8, 32) f32
// sampling_locations: (8, 900, 8, 4, 4, 2) f32
// attention_weights:  (8, 900, 8, 4, 4) f32
// out:                (8, 900, 256) f32
//
// One warp per (b, q, h); lane = channel c. Each corner gather is a fully
// coalesced 128B line (d=32 contiguous f32 per (b,key,h)). All loc/weight
// loads are warp-uniform (1 sector each). 32-bit indexing throughout.

#define MSDA_BS   8
#define MSDA_NQ   900
#define MSDA_NH   8
#define MSDA_D    32
#define MSDA_KEYS 22223
#define KEY_STRIDE (MSDA_NH * MSDA_D)   // 256 floats between consecutive keys

template <int L>
struct Level;
template <> struct Level<0> { static constexpr int H = 100, W = 167, START = 0;     };
template <> struct Level<1> { static constexpr int H = 50,  W = 84,  START = 16700; };
template <> struct Level<2> { static constexpr int H = 25,  W = 42,  START = 20900; };
template <> struct Level<3> { static constexpr int H = 13,  W = 21,  START = 21950; };

template <int L>
__device__ __forceinline__ void sample_level(
    const float* __restrict__ vbase,   // value + b-offset + h*32 + lane
    const float2* __restrict__ locp,   // 16 float2 points for this (b,q,h)
    const float* __restrict__ awp,     // 16 weights
    float& acc)
{
    constexpr int Hd = Level<L>::H;
    constexpr int Wd = Level<L>::W;
    const float* __restrict__ vlev = vbase + Level<L>::START * KEY_STRIDE;

    #pragma unroll
    for (int p = 0; p < 4; p++) {
        const float2 lxy = __ldg(locp + (L * 4 + p));
        const float  w   = __ldg(awp  + (L * 4 + p));

        const float x = lxy.x * (float)Wd - 0.5f;
        const float y = lxy.y * (float)Hd - 0.5f;
        const float xf = floorf(x);
        const float yf = floorf(y);
        const int x0 = (int)xf;
        const int y0 = (int)yf;
        const float wx1 = x - xf;
        const float wy1 = y - yf;
        const float wx0 = 1.0f - wx1;
        const float wy0 = 1.0f - wy1;

        const bool vx0 = (x0 >= 0) && (x0 < Wd);
        const bool vx1 = (x0 >= -1) && (x0 < Wd - 1);
        const bool vy0 = (y0 >= 0) && (y0 < Hd);
        const bool vy1 = (y0 >= -1) && (y0 < Hd - 1);

        // 32-bit: max offset 22223*256 < 2^23
        const int base00 = (y0 * Wd + x0) * KEY_STRIDE;

        // Issue all four corner loads before the FMA chain (MLP=4).
        float v00 = 0.0f, v01 = 0.0f, v10 = 0.0f, v11 = 0.0f;
        if (vy0 && vx0) v00 = __ldg(vlev + base00);
        if (vy0 && vx1) v01 = __ldg(vlev + base00 + KEY_STRIDE);
        if (vy1 && vx0) v10 = __ldg(vlev + base00 + Wd * KEY_STRIDE);
        if (vy1 && vx1) v11 = __ldg(vlev + base00 + Wd * KEY_STRIDE + KEY_STRIDE);

        acc += w * (wy0 * (wx0 * v00 + wx1 * v01) +
                    wy1 * (wx0 * v10 + wx1 * v11));
    }
}

__global__ __launch_bounds__(256) void msda_kernel(
    const float* __restrict__ value,
    const float2* __restrict__ loc,
    const float* __restrict__ aw,
    float* __restrict__ out)
{
    const int warp = (blockIdx.x * blockDim.x + threadIdx.x) >> 5;
    const int lane = threadIdx.x & 31;
    if (warp >= MSDA_BS * MSDA_NQ * MSDA_NH) return;

    const int h  = warp % MSDA_NH;
    const int bq = warp / MSDA_NH;
    const int b  = bq / MSDA_NQ;

    // value element index: ((b*KEYS + key)*8 + h)*32 + c
    const float* __restrict__ vbase =
        value + (size_t)b * (MSDA_KEYS * KEY_STRIDE) + h * MSDA_D + lane;

    const int bqh = warp;  // (b*900 + q)*8 + h == linear warp id
    const float2* __restrict__ locp = loc + (size_t)bqh * 16;  // 16 points (x,y)
    const float*  __restrict__ awp  = aw  + (size_t)bqh * 16;

    float acc = 0.0f;
    sample_level<0>(vbase, locp, awp, acc);
    sample_level<1>(vbase, locp, awp, acc);
    sample_level<2>(vbase, locp, awp, acc);
    sample_level<3>(vbase, locp, awp, acc);

    // out element: ((b*900 + q)*8 + h)*32 + c  ==  (b, q, h*32 + c)
    out[(size_t)bqh * MSDA_D + lane] = acc;
}

extern "C" void kernel_launch(void* const* d_in, const int* in_sizes, int n_in,
                              void* d_out, int out_size)
{
    const float*  value = (const float*)d_in[0];
    const float2* locp  = (const float2*)d_in[1];
    const float*  aw    = (const float*)d_in[2];
    float* out = (float*)d_out;

    const int total_warps = MSDA_BS * MSDA_NQ * MSDA_NH;  // 57600
    const int threads = 256;
    const int blocks = (total_warps * 32 + threads - 1) / threads;  // 7200

    msda_kernel<<<blocks, threads>>>(value, locp, aw, out);
}

// round 3
// speedup vs baseline: 1.3432x; 1.3432x over previous
#include <cuda_runtime.h>

// MultiScaleDeformableAttention (bs=8, nq=900, nh=8, d=32, nl=4, npt=4)
// value:              (8, 22223, 8, 32) f32
// sampling_locations: (8, 900, 8, 4, 4, 2) f32
// attention_weights:  (8, 900, 8, 4, 4) f32
// out:                (8, 900, 256) f32
//
// 4 (b,q,h) units per warp: group = lane>>3, chan-chunk = (lane&7)*4.
// Scalar sampling math executes once per warp for 4 units (SIMT over groups),
// gathers are LDG.128, epilogue uses packed fma.rn.f32x2.
// Border handling is branchless: clamp index, zero the corner weight.

#define MSDA_BS   8
#define MSDA_NQ   900
#define MSDA_NH   8
#define MSDA_D    32
#define MSDA_KEYS 22223
#define KEY_STRIDE 256            // floats between consecutive keys (nh*d)
#define MSDA_UNITS (MSDA_BS * MSDA_NQ * MSDA_NH)   // 57600

typedef unsigned long long u64t;

__device__ __forceinline__ u64t pk2(float a) {
    u64t r;
    asm("mov.b64 %0, {%1, %1};" : "=l"(r) : "f"(a));
    return r;
}
__device__ __forceinline__ void fma2(u64t& d, u64t a, u64t b) {
    asm("fma.rn.f32x2 %0, %1, %2, %0;" : "+l"(d) : "l"(a), "l"(b));
}

template <int L> struct Level;
template <> struct Level<0> { static constexpr int H = 100, W = 167, START = 0;     };
template <> struct Level<1> { static constexpr int H = 50,  W = 84,  START = 16700; };
template <> struct Level<2> { static constexpr int H = 25,  W = 42,  START = 20900; };
template <> struct Level<3> { static constexpr int H = 13,  W = 21,  START = 21950; };

template <int L>
__device__ __forceinline__ void sample_level(
    const float*  __restrict__ vlane,   // value + b-off + h*32 + (lane&7)*4
    const float2* __restrict__ locp,    // 16 points for this unit
    const float*  __restrict__ awp,     // 16 weights for this unit
    u64t& acc0, u64t& acc1)
{
    constexpr int Hd = Level<L>::H;
    constexpr int Wd = Level<L>::W;
    const float* __restrict__ vlev = vlane + Level<L>::START * KEY_STRIDE;

    #pragma unroll
    for (int p = 0; p < 4; p++) {
        const int idx = L * 4 + p;
        const float2 lxy = __ldg(locp + idx);
        const float  w   = __ldg(awp  + idx);

        const float x = fmaf(lxy.x, (float)Wd, -0.5f);
        const float y = fmaf(lxy.y, (float)Hd, -0.5f);
        const int x0 = __float2int_rd(x);   // floor
        const int y0 = __float2int_rd(y);
        const float wx1 = x - (float)x0;
        const float wy1 = y - (float)y0;
        const float wx0 = 1.0f - wx1;
        const float wy0 = 1.0f - wy1;

        // validity: 0 <= idx <= dim-1  (unsigned-compare trick)
        const bool vx0 = (unsigned)x0       < (unsigned)Wd;
        const bool vx1 = (unsigned)(x0 + 1) < (unsigned)Wd;
        const bool vy0 = (unsigned)y0       < (unsigned)Hd;
        const bool vy1 = (unsigned)(y0 + 1) < (unsigned)Hd;

        // clamp indices so the (weight-zeroed) loads stay in bounds
        const int x0c = min(max(x0, 0), Wd - 1);
        const int x1c = min(max(x0 + 1, 0), Wd - 1);
        const int y0c = min(max(y0, 0), Hd - 1);
        const int y1c = min(max(y0 + 1, 0), Hd - 1);

        const int r0 = y0c * Wd;
        const int r1 = y1c * Wd;
        const int o00 = (r0 + x0c) << 8;    // *KEY_STRIDE (floats)
        const int o01 = (r0 + x1c) << 8;
        const int o10 = (r1 + x0c) << 8;
        const int o11 = (r1 + x1c) << 8;

        // four unconditional 128-bit gathers (MLP = 4)
        const ulonglong2 v00 = __ldg((const ulonglong2*)(vlev + o00));
        const ulonglong2 v01 = __ldg((const ulonglong2*)(vlev + o01));
        const ulonglong2 v10 = __ldg((const ulonglong2*)(vlev + o10));
        const ulonglong2 v11 = __ldg((const ulonglong2*)(vlev + o11));

        const float wwy0 = w * wy0;
        const float wwy1 = w * wy1;
        const float c00 = (vx0 && vy0) ? wx0 * wwy0 : 0.0f;
        const float c01 = (vx1 && vy0) ? wx1 * wwy0 : 0.0f;
        const float c10 = (vx0 && vy1) ? wx0 * wwy1 : 0.0f;
        const float c11 = (vx1 && vy1) ? wx1 * wwy1 : 0.0f;

        const u64t p00 = pk2(c00), p01 = pk2(c01), p10 = pk2(c10), p11 = pk2(c11);
        fma2(acc0, p00, v00.x);  fma2(acc1, p00, v00.y);
        fma2(acc0, p01, v01.x);  fma2(acc1, p01, v01.y);
        fma2(acc0, p10, v10.x);  fma2(acc1, p10, v10.y);
        fma2(acc0, p11, v11.x);  fma2(acc1, p11, v11.y);
    }
}

__global__ __launch_bounds__(256) void msda_kernel(
    const float*  __restrict__ value,
    const float2* __restrict__ loc,
    const float*  __restrict__ aw,
    float* __restrict__ out)
{
    const int tid  = blockIdx.x * blockDim.x + threadIdx.x;
    const int lane = threadIdx.x & 31;
    const int warp = tid >> 5;
    const int g    = lane >> 3;            // unit group within warp
    const int u    = warp * 4 + g;         // linear (b,q,h) unit id
    if (u >= MSDA_UNITS) return;
    const int c4 = (lane & 7) << 2;        // channel base (0,4,...,28)

    const int h = u & 7;
    const int b = u / (MSDA_NQ * MSDA_NH); // u / 7200

    const float* __restrict__ vlane =
        value + (size_t)b * (MSDA_KEYS * KEY_STRIDE) + h * MSDA_D + c4;
    const float2* __restrict__ locp = loc + (size_t)u * 16;
    const float*  __restrict__ awp  = aw  + (size_t)u * 16;

    u64t acc0 = 0, acc1 = 0;   // packed {0.f,0.f}
    sample_level<0>(vlane, locp, awp, acc0, acc1);
    sample_level<1>(vlane, locp, awp, acc0, acc1);
    sample_level<2>(vlane, locp, awp, acc0, acc1);
    sample_level<3>(vlane, locp, awp, acc0, acc1);

    float f0, f1, f2, f3;
    asm("mov.b64 {%0, %1}, %2;" : "=f"(f0), "=f"(f1) : "l"(acc0));
    asm("mov.b64 {%0, %1}, %2;" : "=f"(f2), "=f"(f3) : "l"(acc1));

    // out element: u*32 + c4  ==  (b, q, h*32 + c)
    *(float4*)(out + (size_t)u * MSDA_D + c4) = make_float4(f0, f1, f2, f3);
}

extern "C" void kernel_launch(void* const* d_in, const int* in_sizes, int n_in,
                              void* d_out, int out_size)
{
    const float*  value = (const float*)d_in[0];
    const float2* locp  = (const float2*)d_in[1];
    const float*  aw    = (const float*)d_in[2];
    float* out = (float*)d_out;

    const int total_threads = MSDA_UNITS * 8;          // 460800
    const int threads = 256;
    const int blocks = (total_threads + threads - 1) / threads;  // 1800

    msda_kernel<<<blocks, threads>>>(value, locp, aw, out);
}

// round 4
// speedup vs baseline: 1.4302x; 1.0647x over previous
#include <cuda_runtime.h>

// MultiScaleDeformableAttention (bs=8, nq=900, nh=8, d=32, nl=4, npt=4)
// value: (8,22223,8,32) f32 | loc: (8,900,8,4,4,2) f32 | aw: (8,900,8,4,4) f32
// out: (8,900,256) f32
//
// 4 units per warp (group=lane>>3, chan=(lane&7)*4), LDG.128 gathers.
// R4: loc/aw staged in smem (removes global load from per-point dep chain);
// points processed in pairs -> 8 LDG.128 in flight, split f32x2 accumulators.

#define MSDA_NQ   900
#define MSDA_NH   8
#define MSDA_D    32
#define MSDA_KEYS 22223
#define KEY_STRIDE 256
#define MSDA_UNITS (8 * MSDA_NQ * MSDA_NH)   // 57600
#define UNITS_PER_BLOCK 32

typedef unsigned long long u64t;

__device__ __forceinline__ u64t pk2(float a) {
    u64t r; asm("mov.b64 %0, {%1, %1};" : "=l"(r) : "f"(a)); return r;
}
__device__ __forceinline__ void fma2(u64t& d, u64t a, u64t b) {
    asm("fma.rn.f32x2 %0, %1, %2, %0;" : "+l"(d) : "l"(a), "l"(b));
}
__device__ __forceinline__ void add2(u64t& d, u64t a) {
    asm("add.rn.f32x2 %0, %0, %1;" : "+l"(d) : "l"(a));
}

template <int L> struct Level;
template <> struct Level<0> { static constexpr int H = 100, W = 167, START = 0;     };
template <> struct Level<1> { static constexpr int H = 50,  W = 84,  START = 16700; };
template <> struct Level<2> { static constexpr int H = 25,  W = 42,  START = 20900; };
template <> struct Level<3> { static constexpr int H = 13,  W = 21,  START = 21950; };

// Per-point address + corner-coefficient prep (pure ALU, inputs from smem).
template <int Hd, int Wd>
__device__ __forceinline__ void prep(
    const float2 lxy, const float w,
    int& o00, int& o01, int& o10, int& o11,
    float& c00, float& c01, float& c10, float& c11)
{
    const float x = fmaf(lxy.x, (float)Wd, -0.5f);
    const float y = fmaf(lxy.y, (float)Hd, -0.5f);
    const int x0 = __float2int_rd(x);
    const int y0 = __float2int_rd(y);
    const float wx1 = x - (float)x0, wy1 = y - (float)y0;
    const float wx0 = 1.0f - wx1,    wy0 = 1.0f - wy1;

    const bool vx0 = (unsigned)x0       < (unsigned)Wd;
    const bool vx1 = (unsigned)(x0 + 1) < (unsigned)Wd;
    const bool vy0 = (unsigned)y0       < (unsigned)Hd;
    const bool vy1 = (unsigned)(y0 + 1) < (unsigned)Hd;

    const int x0c = min(max(x0, 0), Wd - 1);
    const int x1c = min(max(x0 + 1, 0), Wd - 1);
    const int y0c = min(max(y0, 0), Hd - 1);
    const int y1c = min(max(y0 + 1, 0), Hd - 1);

    const int r0 = y0c * Wd, r1 = y1c * Wd;
    o00 = (r0 + x0c) << 8;  o01 = (r0 + x1c) << 8;
    o10 = (r1 + x0c) << 8;  o11 = (r1 + x1c) << 8;

    const float wwy0 = w * wy0, wwy1 = w * wy1;
    c00 = (vx0 && vy0) ? wx0 * wwy0 : 0.0f;
    c01 = (vx1 && vy0) ? wx1 * wwy0 : 0.0f;
    c10 = (vx0 && vy1) ? wx0 * wwy1 : 0.0f;
    c11 = (vx1 && vy1) ? wx1 * wwy1 : 0.0f;
}

template <int L>
__device__ __forceinline__ void sample_level(
    const float* __restrict__ vlane,
    const float2* __restrict__ locs,   // smem, this unit's 16 points
    const float*  __restrict__ aws,    // smem, this unit's 16 weights
    u64t& a0, u64t& a1, u64t& b0, u64t& b1)
{
    const float* __restrict__ vlev = vlane + Level<L>::START * KEY_STRIDE;

    #pragma unroll
    for (int pp = 0; pp < 2; pp++) {
        const int iA = L * 4 + pp * 2;
        const int iB = iA + 1;

        int aO00, aO01, aO10, aO11;  float aC00, aC01, aC10, aC11;
        int bO00, bO01, bO10, bO11;  float bC00, bC01, bC10, bC11;
        prep<Level<L>::H, Level<L>::W>(locs[iA], aws[iA],
                                       aO00, aO01, aO10, aO11,
                                       aC00, aC01, aC10, aC11);
        prep<Level<L>::H, Level<L>::W>(locs[iB], aws[iB],
                                       bO00, bO01, bO10, bO11,
                                       bC00, bC01, bC10, bC11);

        // 8 independent 128-bit gathers in flight
        const ulonglong2 vA00 = __ldg((const ulonglong2*)(vlev + aO00));
        const ulonglong2 vA01 = __ldg((const ulonglong2*)(vlev + aO01));
        const ulonglong2 vA10 = __ldg((const ulonglong2*)(vlev + aO10));
        const ulonglong2 vA11 = __ldg((const ulonglong2*)(vlev + aO11));
        const ulonglong2 vB00 = __ldg((const ulonglong2*)(vlev + bO00));
        const ulonglong2 vB01 = __ldg((const ulonglong2*)(vlev + bO01));
        const ulonglong2 vB10 = __ldg((const ulonglong2*)(vlev + bO10));
        const ulonglong2 vB11 = __ldg((const ulonglong2*)(vlev + bO11));

        const u64t pA00 = pk2(aC00), pA01 = pk2(aC01), pA10 = pk2(aC10), pA11 = pk2(aC11);
        const u64t pB00 = pk2(bC00), pB01 = pk2(bC01), pB10 = pk2(bC10), pB11 = pk2(bC11);

        fma2(a0, pA00, vA00.x);  fma2(a1, pA00, vA00.y);
        fma2(b0, pB00, vB00.x);  fma2(b1, pB00, vB00.y);
        fma2(a0, pA01, vA01.x);  fma2(a1, pA01, vA01.y);
        fma2(b0, pB01, vB01.x);  fma2(b1, pB01, vB01.y);
        fma2(a0, pA10, vA10.x);  fma2(a1, pA10, vA10.y);
        fma2(b0, pB10, vB10.x);  fma2(b1, pB10, vB10.y);
        fma2(a0, pA11, vA11.x);  fma2(a1, pA11, vA11.y);
        fma2(b0, pB11, vB11.x);  fma2(b1, pB11, vB11.y);
    }
}

__global__ __launch_bounds__(256, 4) void msda_kernel(
    const float*  __restrict__ value,
    const float2* __restrict__ loc,
    const float*  __restrict__ aw,
    float* __restrict__ out)
{
    __shared__ float2 loc_s[UNITS_PER_BLOCK][17];  // pad: groups hit distinct banks
    __shared__ float  aw_s [UNITS_PER_BLOCK][17];

    const int tid = threadIdx.x;
    const int u0  = blockIdx.x * UNITS_PER_BLOCK;

    // Cooperative staging: loc = 32 units * 16 float2 = 256 float4 (1/thread),
    // aw = 32 units * 16 f32 = 128 float4 (first 128 threads).
    {
        const float4 v = __ldg((const float4*)(loc + (size_t)u0 * 16) + tid);
        const int unit = (2 * tid) >> 4;
        const int pos  = (2 * tid) & 15;
        loc_s[unit][pos]     = make_float2(v.x, v.y);
        loc_s[unit][pos + 1] = make_float2(v.z, v.w);
        if (tid < 128) {
            const float4 a = __ldg((const float4*)(aw + (size_t)u0 * 16) + tid);
            const int au = (4 * tid) >> 4;
            const int ap = (4 * tid) & 15;
            aw_s[au][ap]     = a.x;  aw_s[au][ap + 1] = a.y;
            aw_s[au][ap + 2] = a.z;  aw_s[au][ap + 3] = a.w;
        }
    }
    __syncthreads();

    const int lu = tid >> 3;             // local unit 0..31
    const int u  = u0 + lu;              // global (b,q,h) unit
    const int c4 = (tid & 7) << 2;       // channel base

    const int h = u & 7;
    const int b = u / (MSDA_NQ * MSDA_NH);

    const float* __restrict__ vlane =
        value + (size_t)b * (MSDA_KEYS * KEY_STRIDE) + h * MSDA_D + c4;

    u64t a0 = 0, a1 = 0, b0 = 0, b1 = 0;
    sample_level<0>(vlane, loc_s[lu], aw_s[lu], a0, a1, b0, b1);
    sample_level<1>(vlane, loc_s[lu], aw_s[lu], a0, a1, b0, b1);
    sample_level<2>(vlane, loc_s[lu], aw_s[lu], a0, a1, b0, b1);
    sample_level<3>(vlane, loc_s[lu], aw_s[lu], a0, a1, b0, b1);

    add2(a0, b0);
    add2(a1, b1);

    float f0, f1, f2, f3;
    asm("mov.b64 {%0, %1}, %2;" : "=f"(f0), "=f"(f1) : "l"(a0));
    asm("mov.b64 {%0, %1}, %2;" : "=f"(f2), "=f"(f3) : "l"(a1));
    *(float4*)(out + (size_t)u * MSDA_D + c4) = make_float4(f0, f1, f2, f3);
}

extern "C" void kernel_launch(void* const* d_in, const int* in_sizes, int n_in,
                              void* d_out, int out_size)
{
    const float*  value = (const float*)d_in[0];
    const float2* locp  = (const float2*)d_in[1];
    const float*  aw    = (const float*)d_in[2];
    float* out = (float*)d_out;

    const int blocks = MSDA_UNITS / UNITS_PER_BLOCK;   // 1800, exact
    msda_kernel<<<blocks, 256>>>(value, locp, aw, out);
}